// round 1
// baseline (speedup 1.0000x reference)
#include <cuda_runtime.h>

#define TOK  4096
#define Dm   1024
#define Sdim 16
#define Edim 4
#define Hdim 2048
#define Ldim 2048

// ---------------- scratch (device globals; no allocation) ----------------
__device__ float g_delta[(size_t)TOK * Dm];            // 16 MB
__device__ float g_Bm[(size_t)TOK * Sdim];
__device__ float g_Cm[(size_t)TOK * Sdim];
__device__ float g_ssm[(size_t)TOK * Dm];              // 16 MB
__device__ float g_moe[(size_t)TOK * Dm];              // 16 MB
__device__ float g_hidden[(size_t)Edim * TOK * Hdim];  // 128 MB
__device__ int   g_cnt[Edim];
__device__ int   g_idx[Edim * TOK];
__device__ float g_wt[Edim * TOK];

// ---------------- f32x2 helpers ----------------
static __device__ __forceinline__ unsigned long long dup2(float x) {
    unsigned long long r; unsigned u = __float_as_uint(x);
    asm("mov.b64 %0, {%1, %1};" : "=l"(r) : "r"(u));
    return r;
}
static __device__ __forceinline__ void ffma2(unsigned long long& c,
                                             unsigned long long a,
                                             unsigned long long b) {
    asm("fma.rn.f32x2 %0, %1, %2, %0;" : "+l"(c) : "l"(a), "l"(b));
}
union F4U { float4 f4; float f[4]; unsigned long long u2[2]; };

// ---------------- init ----------------
__global__ void k_init() {
    if (threadIdx.x < Edim) g_cnt[threadIdx.x] = 0;
}

// ---------------- generic 128x128x8 fp32 GEMM with mode-specific epilogues --
// MODE 0: g_delta = softplus(x @ W_delta + b_delta)          (M=4096,N=1024,K=1024)
// MODE 1: g_hidden[e] = silu(gather(ssm) @ Wg[e])            (M=cnt[e],N=2048,K=1024)
// MODE 2: g_hidden[e] *= gather(ssm) @ Wu[e]                 (same shape, RMW)
// MODE 3: g_moe[tok] += w * (g_hidden[e] @ Wd[e])            (M=cnt[e],N=1024,K=2048)
template <int MODE>
__global__ __launch_bounds__(256, 2)
void k_gemm(const float* __restrict__ Aext, const float* __restrict__ Bext,
            const float* __restrict__ bias) {
    constexpr int N = (MODE == 1 || MODE == 2) ? Hdim : Dm;
    constexpr int K = (MODE == 3) ? Hdim : Dm;
    const int e = blockIdx.z;

    const float* A; const float* B; int M;
    if (MODE == 0)      { A = Aext;                              B = Bext;                      M = TOK; }
    else if (MODE == 3) { A = g_hidden + (size_t)e * TOK * K;    B = Bext + (size_t)e * K * N;  M = g_cnt[e]; }
    else                { A = g_ssm;                             B = Bext + (size_t)e * K * N;  M = g_cnt[e]; }

    const int m0 = blockIdx.y * 128;
    const int n0 = blockIdx.x * 128;
    if (m0 >= M) return;

    __shared__ float As[8][128];
    __shared__ float Bs[8][128];

    const int tid  = threadIdx.x;
    const int arow = tid >> 1;
    const int acol = (tid & 1) * 4;
    const int brow = tid >> 5;
    const int bcol = (tid & 31) * 4;
    const int tx = tid & 15, ty = tid >> 4;

    bool avalid;
    const float* aptr;
    if (MODE == 1 || MODE == 2) {
        int mr = m0 + arow;
        avalid = mr < M;
        int gr = avalid ? g_idx[e * TOK + mr] : 0;
        aptr = A + (size_t)gr * K + acol;
    } else {
        avalid = (m0 + arow) < M;       // always true for MODE 0
        aptr = A + (size_t)(m0 + arow) * K + acol;
    }
    const float* bptr = B + (size_t)brow * N + n0 + bcol;

    float4 a_ld = avalid ? *(const float4*)aptr : make_float4(0.f, 0.f, 0.f, 0.f);
    float4 b_ld = *(const float4*)bptr;

    unsigned long long acc[8][4];
#pragma unroll
    for (int i = 0; i < 8; i++)
#pragma unroll
        for (int j = 0; j < 4; j++) acc[i][j] = 0ULL;

    const int KT = K / 8;
    for (int kt = 0; kt < KT; kt++) {
        As[acol + 0][arow] = a_ld.x;
        As[acol + 1][arow] = a_ld.y;
        As[acol + 2][arow] = a_ld.z;
        As[acol + 3][arow] = a_ld.w;
        *(float4*)&Bs[brow][bcol] = b_ld;
        __syncthreads();

        if (kt + 1 < KT) {
            a_ld = avalid ? *(const float4*)(aptr + (size_t)(kt + 1) * 8)
                          : make_float4(0.f, 0.f, 0.f, 0.f);
            b_ld = *(const float4*)(bptr + (size_t)(kt + 1) * 8 * N);
        }

#pragma unroll
        for (int k = 0; k < 8; k++) {
            F4U a0, a1, b0, b1;
            a0.f4 = *(const float4*)&As[k][ty * 4];
            a1.f4 = *(const float4*)&As[k][64 + ty * 4];
            b0.f4 = *(const float4*)&Bs[k][tx * 4];
            b1.f4 = *(const float4*)&Bs[k][64 + tx * 4];
            unsigned long long bb0 = b0.u2[0], bb1 = b0.u2[1];
            unsigned long long bb2 = b1.u2[0], bb3 = b1.u2[1];
#pragma unroll
            for (int i = 0; i < 8; i++) {
                float av = (i < 4) ? a0.f[i] : a1.f[i - 4];
                unsigned long long ad = dup2(av);
                ffma2(acc[i][0], ad, bb0);
                ffma2(acc[i][1], ad, bb1);
                ffma2(acc[i][2], ad, bb2);
                ffma2(acc[i][3], ad, bb3);
            }
        }
        __syncthreads();
    }

    // epilogue
#pragma unroll
    for (int i = 0; i < 8; i++) {
        int rloc = (i < 4) ? (ty * 4 + i) : (64 + ty * 4 + (i - 4));
        int r = m0 + rloc;
        if (MODE != 0 && r >= M) continue;
        F4U lo, hi;
        lo.u2[0] = acc[i][0]; lo.u2[1] = acc[i][1];
        hi.u2[0] = acc[i][2]; hi.u2[1] = acc[i][3];
        int c0 = n0 + tx * 4;
        int c1 = n0 + 64 + tx * 4;

        if (MODE == 0) {
            F4U o0, o1;
#pragma unroll
            for (int j = 0; j < 4; j++) {
                float v0 = lo.f[j] + bias[c0 + j];
                float v1 = hi.f[j] + bias[c1 + j];
                o0.f[j] = v0 > 20.f ? v0 : log1pf(__expf(v0));
                o1.f[j] = v1 > 20.f ? v1 : log1pf(__expf(v1));
            }
            *(float4*)&g_delta[(size_t)r * N + c0] = o0.f4;
            *(float4*)&g_delta[(size_t)r * N + c1] = o1.f4;
        } else if (MODE == 1) {
            float* O = g_hidden + (size_t)e * TOK * N;
            F4U o0, o1;
#pragma unroll
            for (int j = 0; j < 4; j++) {
                float v0 = lo.f[j], v1 = hi.f[j];
                o0.f[j] = v0 / (1.f + __expf(-v0));
                o1.f[j] = v1 / (1.f + __expf(-v1));
            }
            *(float4*)&O[(size_t)r * N + c0] = o0.f4;
            *(float4*)&O[(size_t)r * N + c1] = o1.f4;
        } else if (MODE == 2) {
            float* O = g_hidden + (size_t)e * TOK * N;
            F4U o0, o1;
            o0.f4 = *(const float4*)&O[(size_t)r * N + c0];
            o1.f4 = *(const float4*)&O[(size_t)r * N + c1];
#pragma unroll
            for (int j = 0; j < 4; j++) { o0.f[j] *= lo.f[j]; o1.f[j] *= hi.f[j]; }
            *(float4*)&O[(size_t)r * N + c0] = o0.f4;
            *(float4*)&O[(size_t)r * N + c1] = o1.f4;
        } else {
            int tok = g_idx[e * TOK + r];
            float w = g_wt[e * TOK + r];
            float* O = g_moe + (size_t)tok * N;
#pragma unroll
            for (int j = 0; j < 4; j++) {
                atomicAdd(&O[c0 + j], w * lo.f[j]);
                atomicAdd(&O[c1 + j], w * hi.f[j]);
            }
        }
    }
}

// ---------------- Bm / Cm ----------------
__global__ void k_bc(const float* __restrict__ x, const float* __restrict__ WB,
                     const float* __restrict__ WC) {
    __shared__ float xs[Dm];
    __shared__ float red[8][32];
    int n = blockIdx.x, tid = threadIdx.x;
    const float* xr = x + (size_t)n * Dm;
    for (int i = tid; i < Dm; i += 256) xs[i] = xr[i];
    __syncthreads();
    int o = tid & 31, part = tid >> 5;
    const float* W = (o < 16) ? WB : WC;
    int s = o & 15;
    float acc = 0.f;
    int k0 = part * 128;
#pragma unroll 8
    for (int k = 0; k < 128; k++) acc = fmaf(xs[k0 + k], W[(k0 + k) * Sdim + s], acc);
    red[part][o] = acc;
    __syncthreads();
    if (tid < 32) {
        float a = 0.f;
#pragma unroll
        for (int p = 0; p < 8; p++) a += red[p][tid];
        if (tid < 16) g_Bm[n * Sdim + tid] = a;
        else          g_Cm[n * Sdim + (tid - 16)] = a;
    }
}

// ---------------- selective scan: 16 lanes per (b,d) channel ----------------
__global__ void k_scan(const float* __restrict__ x, const float* __restrict__ A_log,
                       const float* __restrict__ Dp) {
    int tid = threadIdx.x;
    int lane = tid & 31;
    int wi = tid >> 5;
    int grp = lane >> 4;
    int s = lane & 15;
    int chan = blockIdx.x * 16 + wi * 2 + grp;   // 0..2047
    int b = chan >> 10;
    int d = chan & 1023;

    float Av = -__expf(A_log[d * Sdim + s]);
    float dpar = Dp[d];
    float h = 0.f;

    size_t tokbase = (size_t)b * Ldim;
    const float* xp  = x       + tokbase * Dm   + d;
    const float* dep = g_delta + tokbase * Dm   + d;
    const float* bp  = g_Bm    + tokbase * Sdim + s;
    const float* cp  = g_Cm    + tokbase * Sdim + s;
    float*       op  = g_ssm   + tokbase * Dm   + d;

    float xb[4], db[4], Bb[4], Cb[4];
#pragma unroll
    for (int q = 0; q < 4; q++) {
        xb[q] = xp[(size_t)q * Dm];  db[q] = dep[(size_t)q * Dm];
        Bb[q] = bp[(size_t)q * Sdim]; Cb[q] = cp[(size_t)q * Sdim];
    }

    for (int t0 = 0; t0 < Ldim; t0 += 4) {
        float xn[4], dn[4], Bn[4], Cn[4];
        if (t0 + 4 < Ldim) {
            const float* xq = xp + (size_t)(t0 + 4) * Dm;
            const float* dq = dep + (size_t)(t0 + 4) * Dm;
            const float* bq = bp + (size_t)(t0 + 4) * Sdim;
            const float* cq = cp + (size_t)(t0 + 4) * Sdim;
#pragma unroll
            for (int q = 0; q < 4; q++) {
                xn[q] = xq[(size_t)q * Dm];  dn[q] = dq[(size_t)q * Dm];
                Bn[q] = bq[(size_t)q * Sdim]; Cn[q] = cq[(size_t)q * Sdim];
            }
        }
#pragma unroll
        for (int q = 0; q < 4; q++) {
            float xt = xb[q], dt = db[q];
            float barA = __expf(fminf(dt * Av, 10.f));
            float barB = fminf(fmaxf(dt * Bb[q], -10.f), 10.f);
            h = fminf(fmaxf(fmaf(barA, h, barB * xt), -10000.f), 10000.f);
            float p = h * Cb[q];
            p += __shfl_xor_sync(0xffffffffu, p, 8, 16);
            p += __shfl_xor_sync(0xffffffffu, p, 4, 16);
            p += __shfl_xor_sync(0xffffffffu, p, 2, 16);
            p += __shfl_xor_sync(0xffffffffu, p, 1, 16);
            if (s == 0) op[(size_t)(t0 + q) * Dm] = p + xt * dpar;
        }
#pragma unroll
        for (int q = 0; q < 4; q++) { xb[q] = xn[q]; db[q] = dn[q]; Bb[q] = Bn[q]; Cb[q] = Cn[q]; }
    }
}

// ---------------- router: softmax over 4 logits, top-2, bucket tokens ----------
__global__ void k_router(const float* __restrict__ Wr) {
    int gw = (blockIdx.x * blockDim.x + threadIdx.x) >> 5;   // token id
    int lane = threadIdx.x & 31;
    const float* xr = g_ssm + (size_t)gw * Dm;
    float a0 = 0, a1 = 0, a2 = 0, a3 = 0;
    for (int k = lane; k < Dm; k += 32) {
        float xv = xr[k];
        float4 w = *(const float4*)&Wr[k * 4];
        a0 = fmaf(xv, w.x, a0); a1 = fmaf(xv, w.y, a1);
        a2 = fmaf(xv, w.z, a2); a3 = fmaf(xv, w.w, a3);
    }
#pragma unroll
    for (int m = 16; m > 0; m >>= 1) {
        a0 += __shfl_xor_sync(~0u, a0, m);
        a1 += __shfl_xor_sync(~0u, a1, m);
        a2 += __shfl_xor_sync(~0u, a2, m);
        a3 += __shfl_xor_sync(~0u, a3, m);
    }
    // zero the moe accumulator row (scatter target of mode-3 GEMM)
    float* mr = g_moe + (size_t)gw * Dm;
    for (int k = lane; k < Dm; k += 32) mr[k] = 0.f;

    if (lane == 0) {
        float l[4] = {a0, a1, a2, a3};
        float mx = fmaxf(fmaxf(l[0], l[1]), fmaxf(l[2], l[3]));
        float p[4]; float Z = 0.f;
#pragma unroll
        for (int q = 0; q < 4; q++) { p[q] = __expf(l[q] - mx); Z += p[q]; }
        float inv = 1.f / Z;
#pragma unroll
        for (int q = 0; q < 4; q++) p[q] *= inv;
        int i0 = 0;
#pragma unroll
        for (int q = 1; q < 4; q++) if (p[q] > p[i0]) i0 = q;
        int i1 = -1;
#pragma unroll
        for (int q = 0; q < 4; q++) if (q != i0 && (i1 < 0 || p[q] > p[i1])) i1 = q;
        float w0 = p[i0], w1 = p[i1];
        float den = w0 + w1 + 1e-9f;
        w0 /= den; w1 /= den;
        int pos0 = atomicAdd(&g_cnt[i0], 1);
        g_idx[i0 * TOK + pos0] = gw; g_wt[i0 * TOK + pos0] = w0;
        int pos1 = atomicAdd(&g_cnt[i1], 1);
        g_idx[i1 * TOK + pos1] = gw; g_wt[i1 * TOK + pos1] = w1;
    }
}

// ---------------- rmsnorm over hidden rows ----------------
__global__ void k_rmsg(const float* __restrict__ wn) {
    int e = blockIdx.y, i = blockIdx.x;
    if (i >= g_cnt[e]) return;
    float* row = g_hidden + ((size_t)e * TOK + i) * Hdim;
    __shared__ float red[8];
    int tid = threadIdx.x, lane = tid & 31, w = tid >> 5;
    float v[8];
    float ss = 0.f;
#pragma unroll
    for (int q = 0; q < 8; q++) { v[q] = row[tid + q * 256]; ss += v[q] * v[q]; }
#pragma unroll
    for (int m = 16; m > 0; m >>= 1) ss += __shfl_xor_sync(~0u, ss, m);
    if (lane == 0) red[w] = ss;
    __syncthreads();
    if (tid == 0) {
        float t = 0.f;
#pragma unroll
        for (int j = 0; j < 8; j++) t += red[j];
        red[0] = rsqrtf(t * (1.f / Hdim) + 1e-6f);
    }
    __syncthreads();
    float r = red[0];
#pragma unroll
    for (int q = 0; q < 8; q++) row[tid + q * 256] = wn[e * Hdim + tid + q * 256] * v[q] * r;
}

// ---------------- final: out = rmsnorm(ssm + moe, norm_w) ----------------
__global__ void k_final(const float* __restrict__ nw, float* __restrict__ out) {
    int n = blockIdx.x;
    int tid = threadIdx.x, lane = tid & 31, w = tid >> 5;
    __shared__ float red[8];
    const float* s = g_ssm + (size_t)n * Dm;
    const float* m = g_moe + (size_t)n * Dm;
    float v[4];
    float ss = 0.f;
#pragma unroll
    for (int q = 0; q < 4; q++) {
        float t = s[tid + q * 256] + m[tid + q * 256];
        v[q] = t; ss += t * t;
    }
#pragma unroll
    for (int mm = 16; mm > 0; mm >>= 1) ss += __shfl_xor_sync(~0u, ss, mm);
    if (lane == 0) red[w] = ss;
    __syncthreads();
    if (tid == 0) {
        float t = 0.f;
#pragma unroll
        for (int j = 0; j < 8; j++) t += red[j];
        red[0] = rsqrtf(t * (1.f / Dm) + 1e-6f);
    }
    __syncthreads();
    float r = red[0];
#pragma unroll
    for (int q = 0; q < 4; q++)
        out[(size_t)n * Dm + tid + q * 256] = nw[tid + q * 256] * v[q] * r;
}

// ---------------- launch ----------------
extern "C" void kernel_launch(void* const* d_in, const int* in_sizes, int n_in,
                              void* d_out, int out_size) {
    const float* x        = (const float*)d_in[0];
    const float* A_log    = (const float*)d_in[1];
    const float* D_param  = (const float*)d_in[2];
    const float* W_delta  = (const float*)d_in[3];
    const float* b_delta  = (const float*)d_in[4];
    const float* W_B      = (const float*)d_in[5];
    const float* W_C      = (const float*)d_in[6];
    const float* W_router = (const float*)d_in[7];
    const float* Wg       = (const float*)d_in[8];
    const float* Wu       = (const float*)d_in[9];
    const float* Wd       = (const float*)d_in[10];
    const float* wn_exp   = (const float*)d_in[11];
    const float* norm_w   = (const float*)d_in[12];
    float* out = (float*)d_out;

    k_init<<<1, 32>>>();
    k_gemm<0><<<dim3(Dm / 128, TOK / 128, 1), 256>>>(x, W_delta, b_delta);
    k_bc<<<TOK, 256>>>(x, W_B, W_C);
    k_scan<<<128, 256>>>(x, A_log, D_param);
    k_router<<<TOK / 8, 256>>>(W_router);
    k_gemm<1><<<dim3(Hdim / 128, TOK / 128, Edim), 256>>>(nullptr, Wg, nullptr);
    k_gemm<2><<<dim3(Hdim / 128, TOK / 128, Edim), 256>>>(nullptr, Wu, nullptr);
    k_rmsg<<<dim3(TOK, Edim), 256>>>(wn_exp);
    k_gemm<3><<<dim3(Dm / 128, TOK / 128, Edim), 256>>>(nullptr, Wd, nullptr);
    k_final<<<TOK, 256>>>(norm_w, out);
}